// round 5
// baseline (speedup 1.0000x reference)
#include <cuda_runtime.h>

// Two-simplicial attention, B=2, S=2048, H=4, D=64, W1=W2=64 (A=C=65).
// 1 position per CTA, 256 threads, 2 CTAs/SM. Phase-4 wide W loads + packed V2.

constexpr int Bc = 2, Sc = 2048, Hc = 4, Dc = 64;
constexpr float SCALE_F = 0.125f;
constexpr int NT = 256;

// ---- smem layout (floats) ----
constexpr int OFF_K1Q = 0;                     // [65][64] q-folded k1
constexpr int OFF_K2T = 65 * 64;               // [64][66] k2 transposed [d][window row]
constexpr int OFF_V1  = OFF_K2T + 64 * 66;     // [65][64]
constexpr int OFF_V2P = OFF_V1 + 65 * 64;      // [33][64][2] (c-pair, d, c-parity)
constexpr int OFF_W   = OFF_V2P + 33 * 128;    // [72][68] (16B-aligned c-quads)
constexpr int OFF_NP  = OFF_W + 72 * 68;       // [8][64]
constexpr int OFF_DEN = OFF_NP + 8 * 64;       // [8]
constexpr int SMEM_FLOATS = OFF_DEN + 8;
constexpr int SMEM_BYTES = SMEM_FLOATS * 4;    // ~88.7 KB -> 2 CTAs/SM

typedef unsigned long long ull;

__device__ __forceinline__ void ffma2(ull& acc, ull a, ull b) {
    asm("fma.rn.f32x2 %0, %1, %2, %0;" : "+l"(acc) : "l"(a), "l"(b));
}
__device__ __forceinline__ ull pack2(float lo, float hi) {
    ull r;
    asm("mov.b64 %0, {%1, %2};" : "=l"(r) : "f"(lo), "f"(hi));
    return r;
}
__device__ __forceinline__ float2 unpack2(ull v) {
    float2 f;
    asm("mov.b64 {%0, %1}, %2;" : "=f"(f.x), "=f"(f.y) : "l"(v));
    return f;
}

__global__ void __launch_bounds__(NT, 2)
tsa_kernel(const float* __restrict__ q,
           const float* __restrict__ k1,
           const float* __restrict__ k2,
           const float* __restrict__ v1,
           const float* __restrict__ v2,
           float* __restrict__ out) {
    extern __shared__ float sm[];
    const int tid = threadIdx.x;
    const int bid = blockIdx.x;
    const int h = bid & 3;
    const int s = (bid >> 2) & 2047;
    const int b = bid >> 13;

    // ---- zero W col 64 for rows 65..71 (read in phase-4 tail, never written) ----
    if (tid < 7) sm[OFF_W + (65 + tid) * 68 + 64] = 0.0f;

    // ================= stage A: loads =================
    const int qb = ((b * Sc + s) * Hc + h) * Dc;
    const int dq = tid & 15;                     // fixed per thread (256 % 16 == 0)
    const float4 qv = *(const float4*)&q[qb + dq * 4];

    for (int i = tid; i < 65 * 16; i += NT) {
        int r = i >> 4;
        int g = s - 64 + r; if (g < 0) g = 0;
        int off = ((b * Sc + g) * Hc + h) * Dc + dq * 4;
        *(float4*)&sm[OFF_V1 + r * 64 + dq * 4] = *(const float4*)&v1[off];

        float4 bv = *(const float4*)&v2[off];
        {   // V2P[c-pair][d][parity]
            float* vp = &sm[OFF_V2P + (r >> 1) * 128 + dq * 8 + (r & 1)];
            vp[0] = bv.x; vp[2] = bv.y; vp[4] = bv.z; vp[6] = bv.w;
        }
        float4 cv = *(const float4*)&k2[off];
        int d0 = dq * 4;
        sm[OFF_K2T + (d0 + 0) * 66 + r] = cv.x;
        sm[OFF_K2T + (d0 + 1) * 66 + r] = cv.y;
        sm[OFF_K2T + (d0 + 2) * 66 + r] = cv.z;
        sm[OFF_K2T + (d0 + 3) * 66 + r] = cv.w;
        float4 kv = *(const float4*)&k1[off];
        kv.x *= qv.x; kv.y *= qv.y; kv.z *= qv.z; kv.w *= qv.w;
        *(float4*)&sm[OFF_K1Q + r * 64 + d0] = kv;
    }
    __syncthreads();

    // ================= phase 3: scores + exp (unchanged from R4) =================
    const int wid = tid >> 5, lane = tid & 31;
    const int a0 = wid * 9;
    const int amin = 64 - s;

    int rowi[9];
#pragma unroll
    for (int i = 0; i < 9; i++) {
        int r = a0 + i;
        rowi[i] = (r > 64) ? 64 : r;
    }

    ull acc[9][2];
#pragma unroll
    for (int i = 0; i < 9; i++) { acc[i][0] = 0ull; acc[i][1] = 0ull; }

    const float* c0 = &sm[OFF_K2T + lane];
    const float* c1 = &sm[OFF_K2T + lane + 32];

#pragma unroll 4
    for (int dqi = 0; dqi < 16; dqi++) {
        int d0 = dqi * 4;
        float c00 = c0[(d0    ) * 66], c01 = c1[(d0    ) * 66];
        float c10 = c0[(d0 + 1) * 66], c11 = c1[(d0 + 1) * 66];
        float c20 = c0[(d0 + 2) * 66], c21 = c1[(d0 + 2) * 66];
        float c30 = c0[(d0 + 3) * 66], c31 = c1[(d0 + 3) * 66];
        ull kA0 = pack2(c00, c10), kA1 = pack2(c01, c11);
        ull kB0 = pack2(c20, c30), kB1 = pack2(c21, c31);
#pragma unroll
        for (int i = 0; i < 9; i++) {
            ulonglong2 a4 = *(const ulonglong2*)&sm[OFF_K1Q + rowi[i] * 64 + d0];
            ffma2(acc[i][0], a4.x, kA0);
            ffma2(acc[i][1], a4.x, kA1);
            ffma2(acc[i][0], a4.y, kB0);
            ffma2(acc[i][1], a4.y, kB1);
        }
    }

    float dloc = 0.0f;
#pragma unroll
    for (int i = 0; i < 9; i++) {
        int a = a0 + i;
        bool av = (a < 65) && (a >= amin);
#pragma unroll
        for (int jc = 0; jc < 2; jc++) {
            int c = lane + 32 * jc;
            float2 t = unpack2(acc[i][jc]);
            float sc = (t.x + t.y) * SCALE_F;
            float wv = 0.0f;
            if (av && c >= amin) { wv = __expf(sc); dloc += wv; }
            sm[OFF_W + a * 68 + c] = wv;   // rows >= 65 get zeros
        }
    }
    // tail column c = 64 (always >= amin)
    {
        float k2a = sm[OFF_K2T + (2 * lane    ) * 66 + 64];
        float k2b = sm[OFF_K2T + (2 * lane + 1) * 66 + 64];
#pragma unroll
        for (int i = 0; i < 9; i++) {
            float2 kf = *(const float2*)&sm[OFF_K1Q + rowi[i] * 64 + lane * 2];
            float t = kf.x * k2a + kf.y * k2b;
#pragma unroll
            for (int o = 16; o; o >>= 1) t += __shfl_xor_sync(0xFFFFFFFFu, t, o);
            if (lane == 0) {
                int a = a0 + i;
                if (a < 65) {
                    float wv = (a >= amin) ? __expf(t * SCALE_F) : 0.0f;
                    dloc += wv;
                    sm[OFF_W + a * 68 + 64] = wv;
                }
            }
        }
    }
#pragma unroll
    for (int o = 16; o; o >>= 1) dloc += __shfl_xor_sync(0xFFFFFFFFu, dloc, o);
    if (lane == 0) sm[OFF_DEN + wid] = dloc;
    __syncwarp();   // each warp reads only its own W rows below

    // ================= phase 4: num = sum_a v1[a] * (W[a,:] @ V2) =================
    ull tmp[9][2];
#pragma unroll
    for (int i = 0; i < 9; i++) { tmp[i][0] = 0ull; tmp[i][1] = 0ull; }

    const float* vb0 = &sm[OFF_V2P + lane * 2];
    const float* vb1 = &sm[OFF_V2P + (lane + 32) * 2];

#pragma unroll 4
    for (int cq = 0; cq < 16; cq++) {
        int cb = cq * 256;                          // 2 c-pairs * 128
        ull vp00 = *(const ull*)(vb0 + cb);         // (V2[c,d], V2[c+1,d])   d=lane
        ull vp01 = *(const ull*)(vb1 + cb);         //                        d=lane+32
        ull vp10 = *(const ull*)(vb0 + cb + 128);   // (V2[c+2,d], V2[c+3,d])
        ull vp11 = *(const ull*)(vb1 + cb + 128);
#pragma unroll
        for (int i = 0; i < 9; i++) {
            ulonglong2 wq = *(const ulonglong2*)&sm[OFF_W + (a0 + i) * 68 + cq * 4];
            ffma2(tmp[i][0], wq.x, vp00);
            ffma2(tmp[i][1], wq.x, vp01);
            ffma2(tmp[i][0], wq.y, vp10);
            ffma2(tmp[i][1], wq.y, vp11);
        }
    }
    // tail c = 64 + v1 contraction
    float v64a = sm[OFF_V2P + 32 * 128 + lane * 2];
    float v64b = sm[OFF_V2P + 32 * 128 + (lane + 32) * 2];
    float ns0 = 0.0f, ns1 = 0.0f;
#pragma unroll
    for (int i = 0; i < 9; i++) {
        float w64 = sm[OFF_W + (a0 + i) * 68 + 64];
        float2 t0 = unpack2(tmp[i][0]);
        float2 t1 = unpack2(tmp[i][1]);
        float ta = t0.x + t0.y + w64 * v64a;
        float tb = t1.x + t1.y + w64 * v64b;
        ta *= sm[OFF_V1 + rowi[i] * 64 + lane];        // invalid rows: all-zero W
        tb *= sm[OFF_V1 + rowi[i] * 64 + lane + 32];
        ns0 += ta;
        ns1 += tb;
    }
    sm[OFF_NP + wid * 64 + lane]      = ns0;
    sm[OFF_NP + wid * 64 + lane + 32] = ns1;
    __syncthreads();

    // ================= epilogue =================
    if (tid < 64) {
        float den = 1e-8f;
#pragma unroll
        for (int w = 0; w < 8; w++) den += sm[OFF_DEN + w];
        float num = 0.0f;
#pragma unroll
        for (int w = 0; w < 8; w++) num += sm[OFF_NP + w * 64 + tid];
        out[qb + tid] = num / den;
    }
}

extern "C" void kernel_launch(void* const* d_in, const int* in_sizes, int n_in,
                              void* d_out, int out_size) {
    const float* q  = (const float*)d_in[0];
    const float* k1 = (const float*)d_in[1];
    const float* k2 = (const float*)d_in[2];
    const float* v1 = (const float*)d_in[3];
    const float* v2 = (const float*)d_in[4];
    float* out = (float*)d_out;

    cudaFuncSetAttribute(tsa_kernel, cudaFuncAttributeMaxDynamicSharedMemorySize,
                         SMEM_BYTES);
    dim3 grid(Bc * Sc * Hc);
    tsa_kernel<<<grid, NT, SMEM_BYTES>>>(q, k1, k2, v1, v2, out);
}

// round 6
// speedup vs baseline: 1.6643x; 1.6643x over previous
#include <cuda_runtime.h>

// Two-simplicial attention, B=2, S=2048, H=4, D=64, W1=W2=64 (A=C=65).
// 1 position per CTA, 256 threads, 2 CTAs/SM.
// R6 = R4 + phase-4 W loads widened to LDS.128 (stride-68 W). V2 unchanged.

constexpr int Bc = 2, Sc = 2048, Hc = 4, Dc = 64;
constexpr float SCALE_F = 0.125f;
constexpr int NT = 256;

// ---- smem layout (floats) ----
constexpr int OFF_K1Q = 0;                    // [65][64] q-folded k1
constexpr int OFF_K2T = 65 * 64;              // [64][66] k2 transposed [d][window row]
constexpr int OFF_V1  = OFF_K2T + 64 * 66;    // [65][64]
constexpr int OFF_V2  = OFF_V1 + 65 * 64;     // [65][64]
constexpr int OFF_W   = OFF_V2 + 65 * 64;     // [72][68] (16B-aligned c-quads)
constexpr int OFF_NP  = OFF_W + 72 * 68;      // [8][64]
constexpr int OFF_DEN = OFF_NP + 8 * 64;      // [8]
constexpr int SMEM_FLOATS = OFF_DEN + 8;
constexpr int SMEM_BYTES = SMEM_FLOATS * 4;   // ~86.4 KB -> 2 CTAs/SM

typedef unsigned long long ull;

__device__ __forceinline__ void ffma2(ull& acc, ull a, ull b) {
    asm("fma.rn.f32x2 %0, %1, %2, %0;" : "+l"(acc) : "l"(a), "l"(b));
}
__device__ __forceinline__ ull pack2(float lo, float hi) {
    ull r;
    asm("mov.b64 %0, {%1, %2};" : "=l"(r) : "f"(lo), "f"(hi));
    return r;
}
__device__ __forceinline__ float2 unpack2(ull v) {
    float2 f;
    asm("mov.b64 {%0, %1}, %2;" : "=f"(f.x), "=f"(f.y) : "l"(v));
    return f;
}

__global__ void __launch_bounds__(NT, 2)
tsa_kernel(const float* __restrict__ q,
           const float* __restrict__ k1,
           const float* __restrict__ k2,
           const float* __restrict__ v1,
           const float* __restrict__ v2,
           float* __restrict__ out) {
    extern __shared__ float sm[];
    const int tid = threadIdx.x;
    const int bid = blockIdx.x;
    const int h = bid & 3;
    const int s = (bid >> 2) & 2047;
    const int b = bid >> 13;

    // ---- zero W cols 64..67 for rows 65..71 (read in phase 4, never written) ----
    if (tid < 28) {
        int rr = 65 + (tid >> 2), cc = 64 + (tid & 3);
        sm[OFF_W + rr * 68 + cc] = 0.0f;
    }

    // ================= stage A: loads =================
    const int qb = ((b * Sc + s) * Hc + h) * Dc;
    const int dq = tid & 15;                     // fixed per thread (256 % 16 == 0)
    const float4 qv = *(const float4*)&q[qb + dq * 4];

    for (int i = tid; i < 65 * 16; i += NT) {
        int r = i >> 4;
        int g = s - 64 + r; if (g < 0) g = 0;
        int off = ((b * Sc + g) * Hc + h) * Dc + dq * 4;
        *(float4*)&sm[OFF_V1 + r * 64 + dq * 4] = *(const float4*)&v1[off];
        *(float4*)&sm[OFF_V2 + r * 64 + dq * 4] = *(const float4*)&v2[off];
        float4 cv = *(const float4*)&k2[off];
        int d0 = dq * 4;
        sm[OFF_K2T + (d0 + 0) * 66 + r] = cv.x;
        sm[OFF_K2T + (d0 + 1) * 66 + r] = cv.y;
        sm[OFF_K2T + (d0 + 2) * 66 + r] = cv.z;
        sm[OFF_K2T + (d0 + 3) * 66 + r] = cv.w;
        float4 kv = *(const float4*)&k1[off];
        kv.x *= qv.x; kv.y *= qv.y; kv.z *= qv.z; kv.w *= qv.w;
        *(float4*)&sm[OFF_K1Q + r * 64 + d0] = kv;
    }
    __syncthreads();

    // ================= phase 3: scores + exp (identical to R4) =================
    const int wid = tid >> 5, lane = tid & 31;
    const int a0 = wid * 9;
    const int amin = 64 - s;

    int rowi[9];
#pragma unroll
    for (int i = 0; i < 9; i++) {
        int r = a0 + i;
        rowi[i] = (r > 64) ? 64 : r;
    }

    ull acc[9][2];
#pragma unroll
    for (int i = 0; i < 9; i++) { acc[i][0] = 0ull; acc[i][1] = 0ull; }

    const float* c0 = &sm[OFF_K2T + lane];
    const float* c1 = &sm[OFF_K2T + lane + 32];

#pragma unroll 4
    for (int dqi = 0; dqi < 16; dqi++) {
        int d0 = dqi * 4;
        float c00 = c0[(d0    ) * 66], c01 = c1[(d0    ) * 66];
        float c10 = c0[(d0 + 1) * 66], c11 = c1[(d0 + 1) * 66];
        float c20 = c0[(d0 + 2) * 66], c21 = c1[(d0 + 2) * 66];
        float c30 = c0[(d0 + 3) * 66], c31 = c1[(d0 + 3) * 66];
        ull kA0 = pack2(c00, c10), kA1 = pack2(c01, c11);
        ull kB0 = pack2(c20, c30), kB1 = pack2(c21, c31);
#pragma unroll
        for (int i = 0; i < 9; i++) {
            ulonglong2 a4 = *(const ulonglong2*)&sm[OFF_K1Q + rowi[i] * 64 + d0];
            ffma2(acc[i][0], a4.x, kA0);
            ffma2(acc[i][1], a4.x, kA1);
            ffma2(acc[i][0], a4.y, kB0);
            ffma2(acc[i][1], a4.y, kB1);
        }
    }

    float dloc = 0.0f;
#pragma unroll
    for (int i = 0; i < 9; i++) {
        int a = a0 + i;
        bool av = (a < 65) && (a >= amin);
#pragma unroll
        for (int jc = 0; jc < 2; jc++) {
            int c = lane + 32 * jc;
            float2 t = unpack2(acc[i][jc]);
            float sc = (t.x + t.y) * SCALE_F;
            float wv = 0.0f;
            if (av && c >= amin) { wv = __expf(sc); dloc += wv; }
            sm[OFF_W + a * 68 + c] = wv;   // rows >= 65 get zeros
        }
    }
    // tail column c = 64 (always >= amin); also zero cols 65..67 pad
    {
        float k2a = sm[OFF_K2T + (2 * lane    ) * 66 + 64];
        float k2b = sm[OFF_K2T + (2 * lane + 1) * 66 + 64];
#pragma unroll
        for (int i = 0; i < 9; i++) {
            float2 kf = *(const float2*)&sm[OFF_K1Q + rowi[i] * 64 + lane * 2];
            float t = kf.x * k2a + kf.y * k2b;
#pragma unroll
            for (int o = 16; o; o >>= 1) t += __shfl_xor_sync(0xFFFFFFFFu, t, o);
            if (lane == 0) {
                int a = a0 + i;
                if (a < 65) {
                    float wv = (a >= amin) ? __expf(t * SCALE_F) : 0.0f;
                    dloc += wv;
                    sm[OFF_W + a * 68 + 64] = wv;
                    sm[OFF_W + a * 68 + 65] = 0.0f;
                    sm[OFF_W + a * 68 + 66] = 0.0f;
                    sm[OFF_W + a * 68 + 67] = 0.0f;
                }
            }
        }
    }
#pragma unroll
    for (int o = 16; o; o >>= 1) dloc += __shfl_xor_sync(0xFFFFFFFFu, dloc, o);
    if (lane == 0) sm[OFF_DEN + wid] = dloc;
    __syncwarp();   // each warp reads only its own W rows below

    // ================= phase 4: num = sum_a v1[a] * (W[a,:] @ V2) =================
    ull tmp[9][2];
#pragma unroll
    for (int i = 0; i < 9; i++) { tmp[i][0] = 0ull; tmp[i][1] = 0ull; }

#pragma unroll 4
    for (int cq = 0; cq < 16; cq++) {
        int c = cq * 4;
        float va0 = sm[OFF_V2 + (c    ) * 64 + lane];
        float va1 = sm[OFF_V2 + (c + 1) * 64 + lane];
        float va2 = sm[OFF_V2 + (c + 2) * 64 + lane];
        float va3 = sm[OFF_V2 + (c + 3) * 64 + lane];
        float vb0 = sm[OFF_V2 + (c    ) * 64 + lane + 32];
        float vb1 = sm[OFF_V2 + (c + 1) * 64 + lane + 32];
        float vb2 = sm[OFF_V2 + (c + 2) * 64 + lane + 32];
        float vb3 = sm[OFF_V2 + (c + 3) * 64 + lane + 32];
        ull vp0 = pack2(va0, va1), vp1 = pack2(va2, va3);
        ull vq0 = pack2(vb0, vb1), vq1 = pack2(vb2, vb3);
#pragma unroll
        for (int i = 0; i < 9; i++) {
            ulonglong2 wq = *(const ulonglong2*)&sm[OFF_W + (a0 + i) * 68 + c];
            ffma2(tmp[i][0], wq.x, vp0);
            ffma2(tmp[i][1], wq.x, vq0);
            ffma2(tmp[i][0], wq.y, vp1);
            ffma2(tmp[i][1], wq.y, vq1);
        }
    }
    // tail c = 64 + v1 contraction
    float v64a = sm[OFF_V2 + 64 * 64 + lane];
    float v64b = sm[OFF_V2 + 64 * 64 + lane + 32];
    float ns0 = 0.0f, ns1 = 0.0f;
#pragma unroll
    for (int i = 0; i < 9; i++) {
        float w64 = sm[OFF_W + (a0 + i) * 68 + 64];
        float2 t0 = unpack2(tmp[i][0]);
        float2 t1 = unpack2(tmp[i][1]);
        float ta = t0.x + t0.y + w64 * v64a;
        float tb = t1.x + t1.y + w64 * v64b;
        ta *= sm[OFF_V1 + rowi[i] * 64 + lane];        // invalid rows: all-zero W
        tb *= sm[OFF_V1 + rowi[i] * 64 + lane + 32];
        ns0 += ta;
        ns1 += tb;
    }
    sm[OFF_NP + wid * 64 + lane]      = ns0;
    sm[OFF_NP + wid * 64 + lane + 32] = ns1;
    __syncthreads();

    // ================= epilogue =================
    if (tid < 64) {
        float den = 1e-8f;
#pragma unroll
        for (int w = 0; w < 8; w++) den += sm[OFF_DEN + w];
        float num = 0.0f;
#pragma unroll
        for (int w = 0; w < 8; w++) num += sm[OFF_NP + w * 64 + tid];
        out[qb + tid] = num / den;
    }
}

extern "C" void kernel_launch(void* const* d_in, const int* in_sizes, int n_in,
                              void* d_out, int out_size) {
    const float* q  = (const float*)d_in[0];
    const float* k1 = (const float*)d_in[1];
    const float* k2 = (const float*)d_in[2];
    const float* v1 = (const float*)d_in[3];
    const float* v2 = (const float*)d_in[4];
    float* out = (float*)d_out;

    cudaFuncSetAttribute(tsa_kernel, cudaFuncAttributeMaxDynamicSharedMemorySize,
                         SMEM_BYTES);
    dim3 grid(Bc * Sc * Hc);
    tsa_kernel<<<grid, NT, SMEM_BYTES>>>(q, k1, k2, v1, v2, out);
}